// round 8
// baseline (speedup 1.0000x reference)
#include <cuda_runtime.h>
#include <cstdint>

// GraphRefiner: 256 graphs x (N=2000, F=2), shared sparse adjacency (E=7998).
// TAGConv(2->64,K=3) -> relu -> TAGConv(64->2,K=3) + residual.
// A (node-space) commutes with W (feature-space): layer-2 is Horner'd in F=2
// space; the 64-wide hidden lives only in registers. One CTA per graph, all
// node state in SMEM, 2 CTAs/SM -> single wave of 256 CTAs.
// R6: z-vectors hoisted into registers across the 16-tile loop (was 16x SMEM
// reload per node); w1/w2 registers phase-split to stay under 128 regs.

#define NNODES 2000
#define EMAX   8192
#define TPB    256
#define BTPB   1024

typedef unsigned long long ull;

// ---- persistent device scratch (no allocations allowed) ----
__device__ int            g_rowptr[NNODES + 1];
__device__ unsigned short g_csr_src16[EMAX];
__device__ float          g_csr_norm[EMAX];

// ======================= fused deterministic CSR build (1 block) =============
__global__ void k_build(const int* __restrict__ row, const int* __restrict__ col,
                        const float* __restrict__ ew, int E) {
    extern __shared__ char bsm[];
    int*            hist = (int*)bsm;                       // 2048 ints
    int*            rp   = hist + 2048;                     // 2048 ints (inclusive scan)
    float*          dinv = (float*)(rp + 2048);             // 2048 floats
    unsigned short* ssrc = (unsigned short*)(dinv + 2048);  // 8192 u16
    float*          sew  = (float*)(ssrc + EMAX);           // 8192 floats

    int tid = threadIdx.x;
    int i0 = tid, i1 = tid + BTPB;

    hist[i0] = 0; hist[i1] = 0;
    __syncthreads();
    for (int e = tid; e < E; e += BTPB) atomicAdd(&hist[col[e]], 1);
    __syncthreads();

    rp[i0] = hist[i0]; rp[i1] = hist[i1];
    __syncthreads();
    for (int off = 1; off < 2048; off <<= 1) {
        int v0 = (i0 >= off) ? rp[i0 - off] : 0;
        int v1 = (i1 >= off) ? rp[i1 - off] : 0;
        __syncthreads();
        rp[i0] += v0; rp[i1] += v1;
        __syncthreads();
    }

    hist[i0] = i0 ? rp[i0 - 1] : 0;
    hist[i1] = rp[i1 - 1];
    __syncthreads();

    for (int e = tid; e < E; e += BTPB) {
        int c = col[e];
        int p = atomicAdd(&hist[c], 1);
        ssrc[p] = (unsigned short)row[e];
        sew[p]  = ew[e];
    }
    __syncthreads();

    // per-node insertion sort by (src, ew-bits) -> canonical order -> bitwise determinism
    for (int n = tid; n < NNODES; n += BTPB) {
        int s = n ? rp[n - 1] : 0;
        int e = rp[n];
        for (int i = s + 1; i < e; ++i) {
            unsigned short ks = ssrc[i];
            float kw = sew[i];
            unsigned kb = __float_as_uint(kw);
            int j = i - 1;
            while (j >= s) {
                unsigned short js = ssrc[j];
                if (js > ks || (js == ks && __float_as_uint(sew[j]) > kb)) {
                    ssrc[j + 1] = js; sew[j + 1] = sew[j]; --j;
                } else break;
            }
            ssrc[j + 1] = ks; sew[j + 1] = kw;
        }
        float w = 0.f;
        for (int i = s; i < e; ++i) w += sew[i];
        dinv[n] = (w > 0.f) ? rsqrtf(w) : 0.f;
        g_rowptr[n + 1] = e;
    }
    if (tid == 0) g_rowptr[0] = 0;
    __syncthreads();

    for (int n = tid; n < NNODES; n += BTPB) {
        int s = n ? rp[n - 1] : 0;
        int e = rp[n];
        float di = dinv[n];
        for (int i = s; i < e; ++i) {
            g_csr_norm[i]  = di * sew[i] * dinv[ssrc[i]];
            g_csr_src16[i] = ssrc[i];
        }
    }
}
#define BUILD_SMEM ((2048 + 2048 + 2048) * 4 + EMAX * 2 + EMAX * 4)

// ======================= main fused kernel ===================================

__device__ __forceinline__ ull pack2(float x, float y) {
    ull r; asm("mov.b64 %0, {%1, %2};" : "=l"(r) : "f"(x), "f"(y)); return r;
}
__device__ __forceinline__ void unpack2(ull v, float& x, float& y) {
    asm("mov.b64 {%0, %1}, %2;" : "=f"(x), "=f"(y) : "l"(v));
}
__device__ __forceinline__ void ffma2(ull& d, ull a, ull b) {
    asm("fma.rn.f32x2 %0, %1, %2, %0;" : "+l"(d) : "l"(a), "l"(b));
}
__device__ __forceinline__ ull add2(ull a, ull b) {
    ull r; asm("add.rn.f32x2 %0, %1, %2;" : "=l"(r) : "l"(a), "l"(b)); return r;
}

// SMEM layout (bytes); all 16B-aligned
#define SM_BUF    0                       // 4 x ull[NNODES] = 64000
#define SM_WTS    (4 * NNODES * 8)        // 544 ull = 4352 (16 tiles x 34 ull)
#define SM_RP     (SM_WTS + 4352)         // (NNODES+2) ints = 8008
#define SM_SRC    (SM_RP + (NNODES + 2) * 4)
#define SM_TOTAL  (SM_SRC + EMAX * 2)     // u16 srcs -> 92744 total

__device__ __forceinline__ void propagate(const ull* __restrict__ src,
                                          ull* __restrict__ dst,
                                          const int* __restrict__ rp,
                                          const unsigned short* __restrict__ ssrc,
                                          bool accum, int tid) {
    for (int n = tid; n < NNODES; n += TPB) {
        int s = rp[n], e = rp[n + 1];
        ull acc0 = accum ? dst[n] : 0ull;
        ull acc1 = 0ull;
        int i = s;
        for (; i + 2 <= e; i += 2) {
            float w0 = __ldg(&g_csr_norm[i]);
            float w1 = __ldg(&g_csr_norm[i + 1]);
            ull v0 = src[ssrc[i]];
            ull v1 = src[ssrc[i + 1]];
            ffma2(acc0, pack2(w0, w0), v0);
            ffma2(acc1, pack2(w1, w1), v1);
        }
        if (i < e) {
            float w0 = __ldg(&g_csr_norm[i]);
            ffma2(acc0, pack2(w0, w0), src[ssrc[i]]);
        }
        dst[n] = add2(acc0, acc1);
    }
}

extern __shared__ char smem[];

__global__ void __launch_bounds__(TPB, 2) k6_main(
    const float* __restrict__ x,
    const float* __restrict__ W1, const float* __restrict__ b1,
    const float* __restrict__ W2, const float* __restrict__ b2,
    float* __restrict__ out, int E)
{
    ull* B0  = (ull*)(smem + SM_BUF);
    ull* B1v = B0 + NNODES;
    ull* B2v = B1v + NNODES;
    ull* B3v = B2v + NNODES;
    ull* wts = (ull*)(smem + SM_WTS);
    int* rp  = (int*)(smem + SM_RP);
    unsigned short* ssrc = (unsigned short*)(smem + SM_SRC);

    int tid = threadIdx.x;
    int g   = blockIdx.x;

    // ---- stage inputs ----
    const ulonglong2* xg2 = (const ulonglong2*)(x + (size_t)g * (2 * NNODES));
    ulonglong2* B02 = (ulonglong2*)B0;
    for (int i = tid; i < NNODES / 2; i += TPB) B02[i] = xg2[i];

    // weights packed per tile t (J=4): [w1t:16][w2t:16][b1t:2] = 34 ull
    //   w1t[i*2+d]  = (W1[i][4t+2d],   W1[i][4t+2d+1])   (i=0..7, d=0..1)
    //   w2t[j*4+q]  = (W2[q][4t+j][0], W2[q][4t+j][1])   (j=0..3, q=0..3)
    //   b1t[d]      = (b1[4t+2d],      b1[4t+2d+1])
    {
        const ull* w1u = (const ull*)W1;
        const ull* w2u = (const ull*)W2;
        const ull* b1u = (const ull*)b1;
        for (int idx = tid; idx < 16 * 34; idx += TPB) {
            int t = idx / 34, r = idx % 34;
            ull v;
            if (r < 16)      { int i = r >> 1, d = r & 1; v = w1u[i * 32 + 2 * t + d]; }
            else if (r < 32) { int rr = r - 16; int j = rr >> 2, q = rr & 3; v = w2u[q * 64 + 4 * t + j]; }
            else             { v = b1u[2 * t + (r - 32)]; }
            wts[idx] = v;
        }
    }
    for (int i = tid; i <= NNODES; i += TPB) rp[i] = g_rowptr[i];
    for (int i = tid; i < E; i += TPB) ssrc[i] = g_csr_src16[i];
    ull b2p = pack2(b2[0], b2[1]);
    __syncthreads();

    // ---- layer-1 hops: z1..z3 ----
    propagate(B0,  B1v, rp, ssrc, false, tid); __syncthreads();
    propagate(B1v, B2v, rp, ssrc, false, tid); __syncthreads();
    propagate(B2v, B3v, rp, ssrc, false, tid); __syncthreads();

    // ---- dense phase: z held in regs across tiles; w1/w2 phase-split ----
    #pragma unroll 1
    for (int strip = 0; strip < 2; ++strip) {
        int nb = tid + strip * 1024;

        // z[m*4+r]: r = hop index, m = node-in-strip. Loaded ONCE per strip.
        ull z[16];
        #pragma unroll
        for (int m = 0; m < 4; ++m) {
            int n = nb + (m << 8);
            if (n >= NNODES) n = 0;              // dummy; write suppressed later
            z[m * 4 + 0] = B0[n];
            z[m * 4 + 1] = B1v[n];
            z[m * 4 + 2] = B2v[n];
            z[m * 4 + 3] = B3v[n];
        }

        ull y[16];
        #pragma unroll
        for (int c = 0; c < 16; ++c) y[c] = 0ull;

        #pragma unroll 1
        for (int t = 0; t < 16; ++t) {
            const ulonglong2* wq = (const ulonglong2*)(wts + t * 34);
            ull w[16], h[8];

            // phase 1: h = z * W1_tile + b1_tile  (w holds w1t)
            #pragma unroll
            for (int c = 0; c < 8; ++c) { ulonglong2 u = wq[c]; w[2*c] = u.x; w[2*c+1] = u.y; }
            ulonglong2 ub = wq[16];
            #pragma unroll
            for (int m = 0; m < 4; ++m) {
                ull h0 = ub.x, h1 = ub.y;
                #pragma unroll
                for (int r = 0; r < 4; ++r) {
                    float za, zb; unpack2(z[m * 4 + r], za, zb);
                    ull bza = pack2(za, za), bzb = pack2(zb, zb);
                    ffma2(h0, bza, w[(2 * r) * 2]);
                    ffma2(h1, bza, w[(2 * r) * 2 + 1]);
                    ffma2(h0, bzb, w[(2 * r + 1) * 2]);
                    ffma2(h1, bzb, w[(2 * r + 1) * 2 + 1]);
                }
                h[m * 2] = h0; h[m * 2 + 1] = h1;
            }

            // phase 2: y += relu(h) * W2_tile  (w reloaded with w2t)
            #pragma unroll
            for (int c = 0; c < 8; ++c) { ulonglong2 u = wq[8 + c]; w[2*c] = u.x; w[2*c+1] = u.y; }
            #pragma unroll
            for (int m = 0; m < 4; ++m) {
                float ha, hb, hc, hd;
                unpack2(h[m * 2], ha, hb); unpack2(h[m * 2 + 1], hc, hd);
                ha = fmaxf(ha, 0.f); hb = fmaxf(hb, 0.f);
                hc = fmaxf(hc, 0.f); hd = fmaxf(hd, 0.f);
                ull d0 = pack2(ha, ha), d1 = pack2(hb, hb);
                ull d2 = pack2(hc, hc), d3 = pack2(hd, hd);
                #pragma unroll
                for (int q = 0; q < 4; ++q) {
                    ull acc = y[m * 4 + q];
                    ffma2(acc, d0, w[q]);
                    ffma2(acc, d1, w[4 + q]);
                    ffma2(acc, d2, w[8 + q]);
                    ffma2(acc, d3, w[12 + q]);
                    y[m * 4 + q] = acc;
                }
            }
        }

        // write back: B3=y3, B2=y2, B1=y1, B0 = x + y0 + b2
        #pragma unroll
        for (int m = 0; m < 4; ++m) {
            int n = nb + (m << 8);
            if (n < NNODES) {
                B3v[n] = y[m * 4 + 3];
                B2v[n] = y[m * 4 + 2];
                B1v[n] = y[m * 4 + 1];
                B0[n]  = add2(z[m * 4], add2(y[m * 4], b2p));
            }
        }
    }
    __syncthreads();

    // ---- layer-2 Horner: B2+=A*B3; B1+=A*B2; B0+=A*B1 ----
    propagate(B3v, B2v, rp, ssrc, true, tid); __syncthreads();
    propagate(B2v, B1v, rp, ssrc, true, tid); __syncthreads();
    propagate(B1v, B0,  rp, ssrc, true, tid); __syncthreads();

    ulonglong2* og2 = (ulonglong2*)(out + (size_t)g * (2 * NNODES));
    const ulonglong2* B0c = (const ulonglong2*)B0;
    for (int i = tid; i < NNODES / 2; i += TPB) og2[i] = B0c[i];
}

// ======================= host launch =========================================

extern "C" void kernel_launch(void* const* d_in, const int* in_sizes, int n_in,
                              void* d_out, int out_size) {
    const float* x   = (const float*)d_in[0];
    const int*   row = (const int*)d_in[1];
    const int*   col = (const int*)d_in[2];
    const float* ew  = (const float*)d_in[3];
    const float* W1  = (const float*)d_in[4];
    const float* b1  = (const float*)d_in[5];
    const float* W2  = (const float*)d_in[6];
    const float* b2  = (const float*)d_in[7];
    float* out = (float*)d_out;

    int E = in_sizes[1];
    int G = out_size / (2 * NNODES);

    cudaFuncSetAttribute(k_build, cudaFuncAttributeMaxDynamicSharedMemorySize, BUILD_SMEM);
    cudaFuncSetAttribute(k6_main, cudaFuncAttributeMaxDynamicSharedMemorySize, SM_TOTAL);

    k_build<<<1, BTPB, BUILD_SMEM>>>(row, col, ew, E);
    k6_main<<<G, TPB, SM_TOTAL>>>(x, W1, b1, W2, b2, out, E);
}